// round 14
// baseline (speedup 1.0000x reference)
#include <cuda_runtime.h>

#define NB 8
#define NX 256
#define NC 256
#define KSEG 8
#define KLEN 32   /* NX / KSEG */
#define KC 8      /* smem chunk depth */
#define NBLK 128  /* grid; <= SM count so the grid barrier is safe */

typedef unsigned long long u64;

// Split-K partial Gram: [seg][b][c*NC+d]  (16 MB, L2-resident)
__device__ float g_G[KSEG * NB * NC * NC];
// Diagonal partials: [b][c][seg]  (64 KB, float4-loadable)
__device__ float g_Sp2[NB * NC * KSEG];
// Grid-barrier ticket counter (monotonic across replays -> deterministic)
__device__ unsigned g_bar;

__device__ __forceinline__ u64 ffma2(u64 a, u64 b, u64 c) {
    u64 d;
    asm("fma.rn.f32x2 %0, %1, %2, %3;" : "=l"(d) : "l"(a), "l"(b), "l"(c));
    return d;
}
__device__ __forceinline__ u64 pack2(float x) {
    u64 d;
    unsigned xi = __float_as_uint(x);
    asm("mov.b64 %0, {%1, %1};" : "=l"(d) : "r"(xi));
    return d;
}

// ---------------------------------------------------------------------------
// Single fused kernel: 128 blocks x 512 threads (1 block/SM, 16 warps/SM).
// Phase 1: Gram tile 128(c) x 256(d) x K=32. One smem buffer (A reads == B
//          buffer since Gram). Warp w owns d-cols [w*16, w*16+16) (uniform ->
//          LDS broadcast); lane owns 4 c-rows. acc = 4x8 u64 (f32x2 pairs).
// Grid barrier (ticket, replay-safe).
// Phase 2: both c-rows of the block concurrently: tid -> (cc, d). Division-
//          free gumbel compare, hybrid __logf + precise-logf fallback.
// ---------------------------------------------------------------------------
__global__ __launch_bounds__(512, 1) void k_fused(const float* __restrict__ amp,
                                                  const float* __restrict__ ph,
                                                  const float* __restrict__ A,
                                                  const float* __restrict__ wap,
                                                  const float* __restrict__ wpp,
                                                  const float* __restrict__ gu,
                                                  float* __restrict__ out) {
    __shared__ __align__(16) float Bs[KC][NC];   // 8 KB
    __shared__ float sS[NB][NC];                  // 8 KB
    __shared__ float red[2][NB][8];               // 512 B

    int tid = threadIdx.x;
    int bid = blockIdx.x;

    // ================= Phase 1: Gram tile =================
    {
        int b = bid >> 4;
        int sub = bid & 15;
        int cBase = (sub & 1) * 128;
        int seg = sub >> 1;            // 0..7
        int k0 = seg * KLEN;
        int w = tid >> 5;              // warp 0..15 -> d cols w*16..w*16+15
        int l = tid & 31;              // lane -> c rows cBase + l*4 .. +3
        int srow = tid >> 6;           // staging row 0..7
        int scol = (tid & 63) * 4;     // staging col 0..252

        float wa = wap[0], wp = wpp[0];
        const float* ab = amp + b * NX * NC;
        const float* pb = ph + b * NX * NC;

        u64 acc[4][8];
#pragma unroll
        for (int i = 0; i < 4; i++)
#pragma unroll
            for (int j = 0; j < 8; j++) acc[i][j] = 0ull;

#pragma unroll 1
        for (int ch = 0; ch < KLEN / KC; ch++) {
            int krow = k0 + ch * KC + srow;
            float4 ra = *(const float4*)(ab + krow * NC + scol);
            float4 rp = *(const float4*)(pb + krow * NC + scol);
            __syncthreads();
            float4 f = make_float4(wa * ra.x + wp * rp.x, wa * ra.y + wp * rp.y,
                                   wa * ra.z + wp * rp.z, wa * ra.w + wp * rp.w);
            *(float4*)&Bs[srow][scol] = f;
            __syncthreads();

#pragma unroll
            for (int k = 0; k < KC; k++) {
                float4 a4 = *(const float4*)&Bs[k][cBase + l * 4];
                const u64* brow = (const u64*)&Bs[k][w * 16];
                u64 b2[8];
#pragma unroll
                for (int j = 0; j < 8; j++) b2[j] = brow[j];
                float av[4] = {a4.x, a4.y, a4.z, a4.w};
#pragma unroll
                for (int i = 0; i < 4; i++) {
                    u64 ai = pack2(av[i]);
#pragma unroll
                    for (int j = 0; j < 8; j++) acc[i][j] = ffma2(ai, b2[j], acc[i][j]);
                }
            }
        }

        // store partial G tile: lane's 4 rows x 16 d-cols (8 u64 each)
        float* Gp = g_G + (seg * NB + b) * (NC * NC);
#pragma unroll
        for (int i = 0; i < 4; i++) {
            int c = cBase + l * 4 + i;
            u64* dst = (u64*)(Gp + c * NC + w * 16);
#pragma unroll
            for (int j = 0; j < 8; j++) dst[j] = acc[i][j];
        }

        // diagonal partials -> g_Sp2[b][c][seg]
#pragma unroll
        for (int i = 0; i < 4; i++) {
            int c = cBase + l * 4 + i;
            if ((c >> 4) == w) {
                int j = (c & 15) >> 1;
                u64 v = acc[i][j];
                float fdi = (c & 1) ? __uint_as_float((unsigned)(v >> 32))
                                    : __uint_as_float((unsigned)(v & 0xffffffffu));
                g_Sp2[(b * NC + c) * KSEG + seg] = fdi;
            }
        }
    }

    // ================= Grid barrier (all 128 blocks co-resident) ==========
    __threadfence();
    __syncthreads();
    if (tid == 0) {
        unsigned v = atomicAdd(&g_bar, 1u);
        unsigned target = (v & ~(unsigned)(NBLK - 1)) + NBLK;
        while (*(volatile unsigned*)&g_bar < target) {
            __nanosleep(32);
        }
    }
    __syncthreads();
    __threadfence();

    // ================= Phase 2: mask ======================================
    // stage sS[b][d] = sum of 8 seg partials (4 entries per thread)
    {
        int e0 = tid * 4;
#pragma unroll
        for (int i = 0; i < 4; i++) {
            int e = e0 + i;                       // = b*256 + d
            const float4* p = (const float4*)(g_Sp2 + e * KSEG);
            float4 x = p[0], y = p[1];
            sS[e >> 8][e & 255] =
                ((x.x + x.y) + (x.z + x.w)) + ((y.x + y.y) + (y.z + y.w));
        }
    }
    __syncthreads();

    int d = tid & 255;
    int cc = tid >> 8;                 // which of the block's 2 c-rows
    int c = bid * 2 + cc;
    int base = c * NC + d;

    float Ad = A[d * (NC + 1)];
    float Ad2 = Ad * Ad;

    // prefetch G sums (64 independent 32-bit-indexed loads) + gumbel pairs
    float Gv[NB];
#pragma unroll
    for (int b2 = 0; b2 < NB; b2++) {
        float s0 = g_G[(0 * NB + b2) * (NC * NC) + base];
        float s1 = g_G[(1 * NB + b2) * (NC * NC) + base];
        float s2 = g_G[(2 * NB + b2) * (NC * NC) + base];
        float s3 = g_G[(3 * NB + b2) * (NC * NC) + base];
        float s4 = g_G[(4 * NB + b2) * (NC * NC) + base];
        float s5 = g_G[(5 * NB + b2) * (NC * NC) + base];
        float s6 = g_G[(6 * NB + b2) * (NC * NC) + base];
        float s7 = g_G[(7 * NB + b2) * (NC * NC) + base];
        Gv[b2] = ((s0 + s1) + (s2 + s3)) + ((s4 + s5) + (s6 + s7));
    }
    float2 uu[NB];
#pragma unroll
    for (int b2 = 0; b2 < NB; b2++)
        uu[b2] = *(const float2*)(gu + 2 * (b2 * (NC * NC) + base));

    float D[NB];
#pragma unroll
    for (int b2 = 0; b2 < NB; b2++) {
        D[b2] = Ad2 * (sS[b2][c] + sS[b2][d] - 2.f * Gv[b2]) + 1e-10f;
        float m = (d == c) ? __int_as_float(0x7f800000) : D[b2];
#pragma unroll
        for (int o = 16; o > 0; o >>= 1)
            m = fminf(m, __shfl_xor_sync(0xffffffffu, m, o));
        if ((tid & 31) == 0) red[cc][b2][(tid >> 5) & 7] = m;
    }
    __syncthreads();

    int cnt = 0;
#pragma unroll
    for (int b2 = 0; b2 < NB; b2++) {
        float Dmin = fminf(
            fminf(fminf(red[cc][b2][0], red[cc][b2][1]),
                  fminf(red[cc][b2][2], red[cc][b2][3])),
            fminf(fminf(red[cc][b2][4], red[cc][b2][5]),
                  fminf(red[cc][b2][6], red[cc][b2][7])));
        // r = num/e; compare r^2*T1 > T0  <=>  num^2*T1 > e^2*T0  (e > 0)
        float num, e;
        if (d == c) {
            num = 0.99f; e = 0.01f;            // p = 0.99 exactly on diagonal
        } else {
            num = 0.99f * Dmin;
            e = D[b2] - num;                   // >= 0.01*Dmin > 0
        }
        float n2 = num * num;
        float e2 = e * e;
        float t0 = -__logf(uu[b2].x);
        float t1 = -__logf(uu[b2].y);
        float L = n2 * t1 - e2 * t0;
        float thr = 1e-6f * (n2 * fmaxf(t1, 1.f) + e2 * fmaxf(t0, 1.f));
        bool take;
        if (fabsf(L) > thr) {
            take = L > 0.f;
        } else {
            float T0 = -logf(uu[b2].x);
            float T1 = -logf(uu[b2].y);
            take = n2 * T1 > e2 * T0;
        }
        if (take) cnt++;
    }
    out[base] = (float)cnt * 0.125f;
}

// ---------------------------------------------------------------------------
extern "C" void kernel_launch(void* const* d_in, const int* in_sizes, int n_in,
                              void* d_out, int out_size) {
    const float* amp = (const float*)d_in[0];
    const float* ph  = (const float*)d_in[1];
    const float* A   = (const float*)d_in[2];
    const float* wa  = (const float*)d_in[3];
    const float* wp  = (const float*)d_in[4];
    const float* gu  = (const float*)d_in[5];
    float* out = (float*)d_out;

    k_fused<<<NBLK, 512>>>(amp, ph, A, wa, wp, gu, out);
}

// round 15
// speedup vs baseline: 1.3778x; 1.3778x over previous
#include <cuda_runtime.h>

#define NB 8
#define NX 256
#define NC 256
#define KSEG 8
#define KLEN 32   /* NX / KSEG */
#define KC 8      /* smem chunk depth */
#define NBLK 256  /* grid; 2 blocks/SM x 148 SMs = 296 >= 256 -> co-resident */

typedef unsigned long long u64;

// Split-K partial Gram: [seg][b][c*NC+d]  (16 MB, L2-resident between phases)
__device__ float g_G[KSEG * NB * NC * NC];
// Diagonal partials: [b][c][seg]  (64 KB, float4-loadable)
__device__ float g_Sp2[NB * NC * KSEG];
// Grid-barrier ticket counter (monotonic across replays -> deterministic)
__device__ unsigned g_bar;

__device__ __forceinline__ u64 ffma2(u64 a, u64 b, u64 c) {
    u64 d;
    asm("fma.rn.f32x2 %0, %1, %2, %3;" : "=l"(d) : "l"(a), "l"(b), "l"(c));
    return d;
}
__device__ __forceinline__ u64 pack2(float x) {
    u64 d;
    unsigned xi = __float_as_uint(x);
    asm("mov.b64 %0, {%1, %1};" : "=l"(d) : "r"(xi));
    return d;
}

// ---------------------------------------------------------------------------
// Fused kernel: 256 blocks x 256 threads, 2 blocks/SM (16 warps/SM).
// Phase 1: R8 Gram tile body, 128x128 x K=32 per block.
//          blockIdx: b = bid>>5, seg = (bid>>2)&7, q = bid&3.
// Grid barrier (ticket, replay-safe).
// Phase 2: one c-row per block (c = bid & 255... wait NBLK=256 -> c = bid),
//          thread = d; 8 batches in registers; division-free compare,
//          hybrid __logf fast path + precise-logf fallback.
// ---------------------------------------------------------------------------
__global__ __launch_bounds__(256, 2) void k_fused(const float* __restrict__ amp,
                                                  const float* __restrict__ ph,
                                                  const float* __restrict__ A,
                                                  const float* __restrict__ wap,
                                                  const float* __restrict__ wpp,
                                                  const float* __restrict__ gu,
                                                  float* __restrict__ out) {
    __shared__ __align__(16) float As[KC][128];
    __shared__ __align__(16) float Bs[KC][128];
    __shared__ float sS[NB][NC];
    __shared__ float red[NB][8];

    int tid = threadIdx.x;
    int bid = blockIdx.x;

    // ================= Phase 1: Gram tile (R8 body, K=32 segment) =========
    {
        int b = bid >> 5;              // batch 0..7
        int seg = (bid >> 2) & 7;      // K segment 0..7
        int q = bid & 3;               // quad
        int cBase = (q >> 1) * 128;
        int dBase = (q & 1) * 128;
        int tx = tid & 15;
        int ty = tid >> 4;
        int sr = tid >> 5;
        int sc = (tid & 31) * 4;

        float wa = wap[0], wp = wpp[0];
        const float* ab = amp + b * NX * NC;
        const float* pb = ph + b * NX * NC;

        u64 acc[8][4];
#pragma unroll
        for (int i = 0; i < 8; i++)
#pragma unroll
            for (int j = 0; j < 4; j++) acc[i][j] = 0ull;

        int k0 = seg * KLEN;

        float4 ra, rp, rb, rq;
        {
            int krow = k0 + sr;
            ra = *(const float4*)(ab + krow * NC + cBase + sc);
            rp = *(const float4*)(pb + krow * NC + cBase + sc);
            rb = *(const float4*)(ab + krow * NC + dBase + sc);
            rq = *(const float4*)(pb + krow * NC + dBase + sc);
        }

#pragma unroll 1
        for (int ch = 0; ch < KLEN / KC; ch++) {
            __syncthreads();
            float4 fa = make_float4(wa * ra.x + wp * rp.x, wa * ra.y + wp * rp.y,
                                    wa * ra.z + wp * rp.z, wa * ra.w + wp * rp.w);
            float4 fb = make_float4(wa * rb.x + wp * rq.x, wa * rb.y + wp * rq.y,
                                    wa * rb.z + wp * rq.z, wa * rb.w + wp * rq.w);
            *(float4*)&As[sr][sc] = fa;
            *(float4*)&Bs[sr][sc] = fb;
            __syncthreads();

            if (ch + 1 < KLEN / KC) {
                int krow = k0 + (ch + 1) * KC + sr;
                ra = *(const float4*)(ab + krow * NC + cBase + sc);
                rp = *(const float4*)(pb + krow * NC + cBase + sc);
                rb = *(const float4*)(ab + krow * NC + dBase + sc);
                rq = *(const float4*)(pb + krow * NC + dBase + sc);
            }

#pragma unroll
            for (int k = 0; k < KC; k++) {
                float4 a0 = *(const float4*)&As[k][ty * 8];
                float4 a1 = *(const float4*)&As[k][ty * 8 + 4];
                const u64* brow = (const u64*)&Bs[k][tx * 8];
                u64 b2v[4];
                b2v[0] = brow[0]; b2v[1] = brow[1]; b2v[2] = brow[2]; b2v[3] = brow[3];
                float av[8] = {a0.x, a0.y, a0.z, a0.w, a1.x, a1.y, a1.z, a1.w};
#pragma unroll
                for (int i = 0; i < 8; i++) {
                    u64 ai = pack2(av[i]);
#pragma unroll
                    for (int j = 0; j < 4; j++) acc[i][j] = ffma2(ai, b2v[j], acc[i][j]);
                }
            }
        }

        float* Gp = g_G + (seg * NB + b) * (NC * NC);
#pragma unroll
        for (int i = 0; i < 8; i++) {
            int c = cBase + ty * 8 + i;
            u64* dst = (u64*)(Gp + c * NC + dBase + tx * 8);
            dst[0] = acc[i][0]; dst[1] = acc[i][1]; dst[2] = acc[i][2]; dst[3] = acc[i][3];
        }

        if (cBase == dBase && tx == ty) {
#pragma unroll
            for (int i = 0; i < 8; i++) {
                int c = cBase + ty * 8 + i;
                u64 v = acc[i][i >> 1];
                float f = (i & 1) ? __uint_as_float((unsigned)(v >> 32))
                                  : __uint_as_float((unsigned)(v & 0xffffffffu));
                g_Sp2[(b * NC + c) * KSEG + seg] = f;
            }
        }
    }

    // ================= Grid barrier (all 256 blocks co-resident) ==========
    __threadfence();
    __syncthreads();
    if (tid == 0) {
        unsigned v = atomicAdd(&g_bar, 1u);
        unsigned target = (v & ~(unsigned)(NBLK - 1)) + NBLK;
        while (*(volatile unsigned*)&g_bar < target) {
            __nanosleep(32);
        }
    }
    __syncthreads();
    __threadfence();

    // ================= Phase 2: mask ======================================
    // stage sS[b][d] = sum of 8 seg partials; 8 entries per thread,
    // conflict-free layout (entry = i*256 + tid)
#pragma unroll
    for (int i = 0; i < 8; i++) {
        int e = i * 256 + tid;                    // = b*256 + d
        const float4* p = (const float4*)(g_Sp2 + e * KSEG);
        float4 x = p[0], y = p[1];
        sS[i][tid] =
            ((x.x + x.y) + (x.z + x.w)) + ((y.x + y.y) + (y.z + y.w));
    }
    __syncthreads();

    int c = bid;                                  // NBLK == NC
    int d = tid;
    int base = c * NC + d;

    float Ad = A[d * (NC + 1)];
    float Ad2 = Ad * Ad;

    // prefetch G sums: 64 independent 32-bit-indexed L2 loads
    float Gv[NB];
#pragma unroll
    for (int b2 = 0; b2 < NB; b2++) {
        float s = 0.f;
        float s0 = g_G[(0 * NB + b2) * (NC * NC) + base];
        float s1 = g_G[(1 * NB + b2) * (NC * NC) + base];
        float s2 = g_G[(2 * NB + b2) * (NC * NC) + base];
        float s3 = g_G[(3 * NB + b2) * (NC * NC) + base];
        float s4 = g_G[(4 * NB + b2) * (NC * NC) + base];
        float s5 = g_G[(5 * NB + b2) * (NC * NC) + base];
        float s6 = g_G[(6 * NB + b2) * (NC * NC) + base];
        float s7 = g_G[(7 * NB + b2) * (NC * NC) + base];
        s = ((s0 + s1) + (s2 + s3)) + ((s4 + s5) + (s6 + s7));
        Gv[b2] = s;
    }
    float2 uu[NB];
#pragma unroll
    for (int b2 = 0; b2 < NB; b2++)
        uu[b2] = *(const float2*)(gu + 2 * (b2 * (NC * NC) + base));

    float D[NB];
#pragma unroll
    for (int b2 = 0; b2 < NB; b2++) {
        D[b2] = Ad2 * (sS[b2][c] + sS[b2][d] - 2.f * Gv[b2]) + 1e-10f;
        float m = (d == c) ? __int_as_float(0x7f800000) : D[b2];
#pragma unroll
        for (int o = 16; o > 0; o >>= 1)
            m = fminf(m, __shfl_xor_sync(0xffffffffu, m, o));
        if ((tid & 31) == 0) red[b2][tid >> 5] = m;
    }
    __syncthreads();

    int cnt = 0;
#pragma unroll
    for (int b2 = 0; b2 < NB; b2++) {
        float Dmin = fminf(
            fminf(fminf(red[b2][0], red[b2][1]), fminf(red[b2][2], red[b2][3])),
            fminf(fminf(red[b2][4], red[b2][5]), fminf(red[b2][6], red[b2][7])));
        // r = num/e; compare r^2*T1 > T0  <=>  num^2*T1 > e^2*T0  (e > 0)
        float num, e;
        if (d == c) {
            num = 0.99f; e = 0.01f;            // p = 0.99 exactly on diagonal
        } else {
            num = 0.99f * Dmin;
            e = D[b2] - num;                   // >= 0.01*Dmin > 0
        }
        float n2 = num * num;
        float e2 = e * e;
        float t0 = -__logf(uu[b2].x);
        float t1 = -__logf(uu[b2].y);
        float L = n2 * t1 - e2 * t0;
        float thr = 1e-6f * (n2 * fmaxf(t1, 1.f) + e2 * fmaxf(t0, 1.f));
        bool take;
        if (fabsf(L) > thr) {
            take = L > 0.f;
        } else {
            float T0 = -logf(uu[b2].x);
            float T1 = -logf(uu[b2].y);
            take = n2 * T1 > e2 * T0;
        }
        if (take) cnt++;
    }
    out[base] = (float)cnt * 0.125f;
}

// ---------------------------------------------------------------------------
extern "C" void kernel_launch(void* const* d_in, const int* in_sizes, int n_in,
                              void* d_out, int out_size) {
    const float* amp = (const float*)d_in[0];
    const float* ph  = (const float*)d_in[1];
    const float* A   = (const float*)d_in[2];
    const float* wa  = (const float*)d_in[3];
    const float* wp  = (const float*)d_in[4];
    const float* gu  = (const float*)d_in[5];
    float* out = (float*)d_out;

    k_fused<<<NBLK, 256>>>(amp, ph, A, wa, wp, gu, out);
}

// round 16
// speedup vs baseline: 1.4735x; 1.0694x over previous
#include <cuda_runtime.h>

#define NB 8
#define NX 256
#define NC 256
#define KSEG 8
#define KLEN 32   /* NX / KSEG */
#define KC 8      /* smem chunk depth */

typedef unsigned long long u64;

// Split-K partial Gram: [seg][b][c*NC+d]  (16 MB)
__device__ float g_G[KSEG * NB * NC * NC];
// Diagonal partials: [b][c][seg]  (64 KB, 2x float4 per (b,c))
__device__ float g_Sp2[NB * NC * KSEG];

__device__ __forceinline__ u64 ffma2(u64 a, u64 b, u64 c) {
    u64 d;
    asm("fma.rn.f32x2 %0, %1, %2, %3;" : "=l"(d) : "l"(a), "l"(b), "l"(c));
    return d;
}
__device__ __forceinline__ u64 pack2(float x) {
    u64 d;
    unsigned xi = __float_as_uint(x);
    asm("mov.b64 %0, {%1, %1};" : "=l"(d) : "r"(xi));
    return d;
}

// ---------------------------------------------------------------------------
// K1: partial Gram over K-segment of 32. R8 body unchanged; KSEG=8 gives
//     256 blocks -> 2 blocks/SM (4 warps/SMSP) so LDS and FFMA2 streams of
//     independent blocks interleave. grid = (32, 8): x = seg*4+quad, y = b.
// ---------------------------------------------------------------------------
__global__ __launch_bounds__(256, 2) void k_gram(const float* __restrict__ amp,
                                                 const float* __restrict__ ph,
                                                 const float* __restrict__ wap,
                                                 const float* __restrict__ wpp) {
    __shared__ __align__(16) float As[KC][128];
    __shared__ __align__(16) float Bs[KC][128];

    int b = blockIdx.y;
    int q = blockIdx.x & 3;
    int seg = blockIdx.x >> 2;      // 0..7
    int cBase = (q >> 1) * 128;
    int dBase = (q & 1) * 128;
    int tid = threadIdx.x;
    int tx = tid & 15;
    int ty = tid >> 4;
    int sr = tid >> 5;
    int sc = (tid & 31) * 4;

    float wa = wap[0], wp = wpp[0];
    const float* ab = amp + b * NX * NC;
    const float* pb = ph + b * NX * NC;

    u64 acc[8][4];
#pragma unroll
    for (int i = 0; i < 8; i++)
#pragma unroll
        for (int j = 0; j < 4; j++) acc[i][j] = 0ull;

    int k0 = seg * KLEN;

    float4 ra, rp, rb, rq;
    {
        int krow = k0 + sr;
        ra = *(const float4*)(ab + krow * NC + cBase + sc);
        rp = *(const float4*)(pb + krow * NC + cBase + sc);
        rb = *(const float4*)(ab + krow * NC + dBase + sc);
        rq = *(const float4*)(pb + krow * NC + dBase + sc);
    }

#pragma unroll 1
    for (int ch = 0; ch < KLEN / KC; ch++) {
        __syncthreads();
        float4 fa = make_float4(wa * ra.x + wp * rp.x, wa * ra.y + wp * rp.y,
                                wa * ra.z + wp * rp.z, wa * ra.w + wp * rp.w);
        float4 fb = make_float4(wa * rb.x + wp * rq.x, wa * rb.y + wp * rq.y,
                                wa * rb.z + wp * rq.z, wa * rb.w + wp * rq.w);
        *(float4*)&As[sr][sc] = fa;
        *(float4*)&Bs[sr][sc] = fb;
        __syncthreads();

        if (ch + 1 < KLEN / KC) {
            int krow = k0 + (ch + 1) * KC + sr;
            ra = *(const float4*)(ab + krow * NC + cBase + sc);
            rp = *(const float4*)(pb + krow * NC + cBase + sc);
            rb = *(const float4*)(ab + krow * NC + dBase + sc);
            rq = *(const float4*)(pb + krow * NC + dBase + sc);
        }

#pragma unroll
        for (int k = 0; k < KC; k++) {
            float4 a0 = *(const float4*)&As[k][ty * 8];
            float4 a1 = *(const float4*)&As[k][ty * 8 + 4];
            const u64* brow = (const u64*)&Bs[k][tx * 8];
            u64 b2v[4];
            b2v[0] = brow[0]; b2v[1] = brow[1]; b2v[2] = brow[2]; b2v[3] = brow[3];
            float av[8] = {a0.x, a0.y, a0.z, a0.w, a1.x, a1.y, a1.z, a1.w};
#pragma unroll
            for (int i = 0; i < 8; i++) {
                u64 ai = pack2(av[i]);
#pragma unroll
                for (int j = 0; j < 4; j++) acc[i][j] = ffma2(ai, b2v[j], acc[i][j]);
            }
        }
    }

    float* Gp = g_G + (seg * NB + b) * (NC * NC);
#pragma unroll
    for (int i = 0; i < 8; i++) {
        int c = cBase + ty * 8 + i;
        u64* dst = (u64*)(Gp + c * NC + dBase + tx * 8);
        dst[0] = acc[i][0]; dst[1] = acc[i][1]; dst[2] = acc[i][2]; dst[3] = acc[i][3];
    }

    if (cBase == dBase && tx == ty) {
#pragma unroll
        for (int i = 0; i < 8; i++) {
            int c = cBase + ty * 8 + i;
            u64 v = acc[i][i >> 1];
            float f = (i & 1) ? __uint_as_float((unsigned)(v >> 32))
                              : __uint_as_float((unsigned)(v & 0xffffffffu));
            g_Sp2[(b * NC + c) * KSEG + seg] = f;
        }
    }
}

// ---------------------------------------------------------------------------
// K2: grid = 256 (c), block = 1024 = (d:256) x (bq:4); thread handles
//     b = bq and b = bq+4. 16 independent G loads + 4 float4 S loads +
//     2 gumbel float2 per thread. Division-free gumbel compare with hybrid
//     __logf fast path + precise-logf fallback (decisions bit-identical).
//     Per-b block min via shuffle + smem. No atomics, no zeroing.
// ---------------------------------------------------------------------------
__global__ __launch_bounds__(1024) void k_mask(const float* __restrict__ A,
                                               const float* __restrict__ gu,
                                               float* __restrict__ out) {
    int c = blockIdx.x;
    int tid = threadIdx.x;
    int d = tid & 255;
    int bq = tid >> 8;                 // 0..3 ; batches bq and bq+4
    __shared__ float scs[NB];          // Sc per batch
    __shared__ float red[NB][8];       // per-b warp minima
    __shared__ int scnt[4][NC];

    float Ad = A[d * (NC + 1)];
    float Ad2 = Ad * Ad;

    float Gv[2], Sd[2];
#pragma unroll
    for (int h = 0; h < 2; h++) {
        int b = bq + h * 4;
        int base = b * (NC * NC) + c * NC + d;
        float s0 = g_G[0 * (NB * NC * NC) + base];
        float s1 = g_G[1 * (NB * NC * NC) + base];
        float s2 = g_G[2 * (NB * NC * NC) + base];
        float s3 = g_G[3 * (NB * NC * NC) + base];
        float s4 = g_G[4 * (NB * NC * NC) + base];
        float s5 = g_G[5 * (NB * NC * NC) + base];
        float s6 = g_G[6 * (NB * NC * NC) + base];
        float s7 = g_G[7 * (NB * NC * NC) + base];
        Gv[h] = ((s0 + s1) + (s2 + s3)) + ((s4 + s5) + (s6 + s7));
        const float4* sp = (const float4*)(g_Sp2 + (b * NC + d) * KSEG);
        float4 x = sp[0], y = sp[1];
        Sd[h] = ((x.x + x.y) + (x.z + x.w)) + ((y.x + y.y) + (y.z + y.w));
        if (d == c) scs[b] = Sd[h];
    }
    float2 uu[2];
#pragma unroll
    for (int h = 0; h < 2; h++) {
        int b = bq + h * 4;
        uu[h] = *(const float2*)(gu + 2 * (b * (NC * NC) + c * NC + d));
    }
    __syncthreads();

    float D[2];
#pragma unroll
    for (int h = 0; h < 2; h++) {
        int b = bq + h * 4;
        D[h] = Ad2 * (scs[b] + Sd[h] - 2.f * Gv[h]) + 1e-10f;
        float m = (d == c) ? __int_as_float(0x7f800000) : D[h];
#pragma unroll
        for (int o = 16; o > 0; o >>= 1)
            m = fminf(m, __shfl_xor_sync(0xffffffffu, m, o));
        if ((d & 31) == 0) red[b][(d >> 5)] = m;
    }
    __syncthreads();

    int cnt[2] = {0, 0};
#pragma unroll
    for (int h = 0; h < 2; h++) {
        int b = bq + h * 4;
        float Dmin = fminf(
            fminf(fminf(red[b][0], red[b][1]), fminf(red[b][2], red[b][3])),
            fminf(fminf(red[b][4], red[b][5]), fminf(red[b][6], red[b][7])));
        // r = num/e; compare r^2*T1 > T0  <=>  num^2*T1 > e^2*T0  (e > 0)
        float num, e;
        if (d == c) {
            num = 0.99f; e = 0.01f;            // p = 0.99 exactly on diagonal
        } else {
            num = 0.99f * Dmin;
            e = D[h] - num;                    // >= 0.01*Dmin > 0
        }
        float n2 = num * num;
        float e2 = e * e;
        float t0 = -__logf(uu[h].x);
        float t1 = -__logf(uu[h].y);
        float L = n2 * t1 - e2 * t0;
        float thr = 1e-6f * (n2 * fmaxf(t1, 1.f) + e2 * fmaxf(t0, 1.f));
        bool take;
        if (fabsf(L) > thr) {
            take = L > 0.f;
        } else {
            float T0 = -logf(uu[h].x);
            float T1 = -logf(uu[h].y);
            take = n2 * T1 > e2 * T0;
        }
        if (take) cnt[h]++;
    }

    scnt[bq][d] = cnt[0] + cnt[1];
    __syncthreads();
    if (bq == 0)
        out[c * NC + d] = (float)(scnt[0][d] + scnt[1][d] +
                                  scnt[2][d] + scnt[3][d]) * 0.125f;
}

// ---------------------------------------------------------------------------
extern "C" void kernel_launch(void* const* d_in, const int* in_sizes, int n_in,
                              void* d_out, int out_size) {
    const float* amp = (const float*)d_in[0];
    const float* ph  = (const float*)d_in[1];
    const float* A   = (const float*)d_in[2];
    const float* wa  = (const float*)d_in[3];
    const float* wp  = (const float*)d_in[4];
    const float* gu  = (const float*)d_in[5];
    float* out = (float*)d_out;

    k_gram<<<dim3(32, NB), 256>>>(amp, ph, wa, wp);
    k_mask<<<NC, 1024>>>(A, gu, out);
}

// round 17
// speedup vs baseline: 1.4904x; 1.0115x over previous
#include <cuda_runtime.h>

#define NB 8
#define NX 256
#define NC 256
#define KSEG 4
#define KLEN 64   /* NX / KSEG */
#define KC 8      /* smem chunk depth */

typedef unsigned long long u64;

// Split-K partial Gram: [seg][b][c*NC+d]  (8 MB)
__device__ float g_G[KSEG * NB * NC * NC];
// Diagonal partials: [b][c][seg]  (32 KB, one float4 per (b,c))
__device__ float g_Sp2[NB * NC * KSEG];

__device__ __forceinline__ u64 ffma2(u64 a, u64 b, u64 c) {
    u64 d;
    asm("fma.rn.f32x2 %0, %1, %2, %3;" : "=l"(d) : "l"(a), "l"(b), "l"(c));
    return d;
}
__device__ __forceinline__ u64 pack2(float x) {
    u64 d;
    unsigned xi = __float_as_uint(x);
    asm("mov.b64 %0, {%1, %1};" : "=l"(d) : "r"(xi));
    return d;
}

// ---------------------------------------------------------------------------
// K1: partial Gram over K-segment of 64. 128x128 tile, 512 threads,
//     4(c) x 8(d) micro-tile -> acc = 16 u64 (~70 regs, no cap needed).
//     16 warps/SM = 4 warps/SMSP: FFMA2 issue floor unchanged, LDS stalls
//     hidden. Staging: threads 0-255 fill A, 256-511 fill B (1 float4 each).
//     grid = (16, 8): x = seg*4 + quad, y = b.
// ---------------------------------------------------------------------------
__global__ __launch_bounds__(512) void k_gram(const float* __restrict__ amp,
                                              const float* __restrict__ ph,
                                              const float* __restrict__ wap,
                                              const float* __restrict__ wpp) {
    __shared__ __align__(16) float As[KC][128];
    __shared__ __align__(16) float Bs[KC][128];

    int b = blockIdx.y;
    int q = blockIdx.x & 3;
    int seg = blockIdx.x >> 2;      // 0..3
    int cBase = (q >> 1) * 128;
    int dBase = (q & 1) * 128;
    int tid = threadIdx.x;
    int tx = tid & 15;              // d group: cols tx*8 .. tx*8+7
    int ty = tid >> 4;              // c group 0..31: rows ty*4 .. ty*4+3

    // staging role: first 256 threads -> A (cBase), rest -> B (dBase)
    int half = tid >> 8;
    int sr = (tid >> 5) & 7;        // chunk row 0..7
    int sc = (tid & 31) * 4;        // col 0..124
    int sBase = half ? dBase : cBase;
    float* sdst = half ? &Bs[0][0] : &As[0][0];

    float wa = wap[0], wp = wpp[0];
    const float* ab = amp + b * NX * NC;
    const float* pb = ph + b * NX * NC;

    u64 acc[4][4];
#pragma unroll
    for (int i = 0; i < 4; i++)
#pragma unroll
        for (int j = 0; j < 4; j++) acc[i][j] = 0ull;

    int k0 = seg * KLEN;

    float4 ra, rp;
    {
        int krow = k0 + sr;
        ra = *(const float4*)(ab + krow * NC + sBase + sc);
        rp = *(const float4*)(pb + krow * NC + sBase + sc);
    }

#pragma unroll 1
    for (int ch = 0; ch < KLEN / KC; ch++) {
        __syncthreads();
        float4 f = make_float4(wa * ra.x + wp * rp.x, wa * ra.y + wp * rp.y,
                               wa * ra.z + wp * rp.z, wa * ra.w + wp * rp.w);
        *(float4*)(sdst + sr * 128 + sc) = f;
        __syncthreads();

        if (ch + 1 < KLEN / KC) {
            int krow = k0 + (ch + 1) * KC + sr;
            ra = *(const float4*)(ab + krow * NC + sBase + sc);
            rp = *(const float4*)(pb + krow * NC + sBase + sc);
        }

#pragma unroll
        for (int k = 0; k < KC; k++) {
            float4 a4 = *(const float4*)&As[k][ty * 4];
            const u64* brow = (const u64*)&Bs[k][tx * 8];
            u64 b2v[4];
            b2v[0] = brow[0]; b2v[1] = brow[1]; b2v[2] = brow[2]; b2v[3] = brow[3];
            float av[4] = {a4.x, a4.y, a4.z, a4.w};
#pragma unroll
            for (int i = 0; i < 4; i++) {
                u64 ai = pack2(av[i]);
#pragma unroll
                for (int j = 0; j < 4; j++) acc[i][j] = ffma2(ai, b2v[j], acc[i][j]);
            }
        }
    }

    float* Gp = g_G + (seg * NB + b) * (NC * NC);
#pragma unroll
    for (int i = 0; i < 4; i++) {
        int c = cBase + ty * 4 + i;
        u64* dst = (u64*)(Gp + c * NC + dBase + tx * 8);
        dst[0] = acc[i][0]; dst[1] = acc[i][1]; dst[2] = acc[i][2]; dst[3] = acc[i][3];
    }

    // diagonal partials -> g_Sp2[b][c][seg]
    if (cBase == dBase) {
#pragma unroll
        for (int i = 0; i < 4; i++) {
            int cl = ty * 4 + i;           // local row 0..127
            if ((cl >> 3) == tx) {         // this thread's d-range covers cl
                int j = (cl & 7) >> 1;
                u64 v = acc[i][j];
                float f = (cl & 1) ? __uint_as_float((unsigned)(v >> 32))
                                   : __uint_as_float((unsigned)(v & 0xffffffffu));
                g_Sp2[(b * NC + cBase + cl) * KSEG + seg] = f;
            }
        }
    }
}

// ---------------------------------------------------------------------------
// K2: grid = 256 (c), block = 1024 = (d:256) x (bq:4); thread handles
//     b = bq and b = bq+4. Division-free gumbel compare with hybrid __logf
//     fast path + precise-logf fallback (decisions bit-identical).
//     (R16 body, adapted to KSEG=4.)
// ---------------------------------------------------------------------------
__global__ __launch_bounds__(1024) void k_mask(const float* __restrict__ A,
                                               const float* __restrict__ gu,
                                               float* __restrict__ out) {
    int c = blockIdx.x;
    int tid = threadIdx.x;
    int d = tid & 255;
    int bq = tid >> 8;                 // 0..3 ; batches bq and bq+4
    __shared__ float scs[NB];          // Sc per batch
    __shared__ float red[NB][8];       // per-b warp minima
    __shared__ int scnt[4][NC];

    float Ad = A[d * (NC + 1)];
    float Ad2 = Ad * Ad;

    float Gv[2], Sd[2];
#pragma unroll
    for (int h = 0; h < 2; h++) {
        int b = bq + h * 4;
        int base = b * (NC * NC) + c * NC + d;
        float s0 = g_G[0 * (NB * NC * NC) + base];
        float s1 = g_G[1 * (NB * NC * NC) + base];
        float s2 = g_G[2 * (NB * NC * NC) + base];
        float s3 = g_G[3 * (NB * NC * NC) + base];
        Gv[h] = (s0 + s1) + (s2 + s3);
        float4 x = *(const float4*)(g_Sp2 + (b * NC + d) * KSEG);
        Sd[h] = (x.x + x.y) + (x.z + x.w);
        if (d == c) scs[b] = Sd[h];
    }
    float2 uu[2];
#pragma unroll
    for (int h = 0; h < 2; h++) {
        int b = bq + h * 4;
        uu[h] = *(const float2*)(gu + 2 * (b * (NC * NC) + c * NC + d));
    }
    __syncthreads();

    float D[2];
#pragma unroll
    for (int h = 0; h < 2; h++) {
        int b = bq + h * 4;
        D[h] = Ad2 * (scs[b] + Sd[h] - 2.f * Gv[h]) + 1e-10f;
        float m = (d == c) ? __int_as_float(0x7f800000) : D[h];
#pragma unroll
        for (int o = 16; o > 0; o >>= 1)
            m = fminf(m, __shfl_xor_sync(0xffffffffu, m, o));
        if ((d & 31) == 0) red[b][(d >> 5)] = m;
    }
    __syncthreads();

    int cnt = 0;
#pragma unroll
    for (int h = 0; h < 2; h++) {
        int b = bq + h * 4;
        float Dmin = fminf(
            fminf(fminf(red[b][0], red[b][1]), fminf(red[b][2], red[b][3])),
            fminf(fminf(red[b][4], red[b][5]), fminf(red[b][6], red[b][7])));
        // r = num/e; compare r^2*T1 > T0  <=>  num^2*T1 > e^2*T0  (e > 0)
        float num, e;
        if (d == c) {
            num = 0.99f; e = 0.01f;            // p = 0.99 exactly on diagonal
        } else {
            num = 0.99f * Dmin;
            e = D[h] - num;                    // >= 0.01*Dmin > 0
        }
        float n2 = num * num;
        float e2 = e * e;
        float t0 = -__logf(uu[h].x);
        float t1 = -__logf(uu[h].y);
        float L = n2 * t1 - e2 * t0;
        float thr = 1e-6f * (n2 * fmaxf(t1, 1.f) + e2 * fmaxf(t0, 1.f));
        bool take;
        if (fabsf(L) > thr) {
            take = L > 0.f;
        } else {
            float T0 = -logf(uu[h].x);
            float T1 = -logf(uu[h].y);
            take = n2 * T1 > e2 * T0;
        }
        if (take) cnt++;
    }

    scnt[bq][d] = cnt;
    __syncthreads();
    if (bq == 0)
        out[c * NC + d] = (float)(scnt[0][d] + scnt[1][d] +
                                  scnt[2][d] + scnt[3][d]) * 0.125f;
}

// ---------------------------------------------------------------------------
extern "C" void kernel_launch(void* const* d_in, const int* in_sizes, int n_in,
                              void* d_out, int out_size) {
    const float* amp = (const float*)d_in[0];
    const float* ph  = (const float*)d_in[1];
    const float* A   = (const float*)d_in[2];
    const float* wa  = (const float*)d_in[3];
    const float* wp  = (const float*)d_in[4];
    const float* gu  = (const float*)d_in[5];
    float* out = (float*)d_out;

    k_gram<<<dim3(16, NB), 512>>>(amp, ph, wa, wp);
    k_mask<<<NC, 1024>>>(A, gu, out);
}